// round 12
// baseline (speedup 1.0000x reference)
#include <cuda_runtime.h>

#define B_   16
#define T_   512
#define C_   8
#define S_   64
#define KSZ_ 32
#define TOUT 481
#define EPSF 1e-8f

// Scratch (allocation-free rule: __device__ globals). g_xt padded +64 so the
// 4x float4 window loads at the t-edge stay in-bounds (values masked at store).
__device__ float g_xt[B_ * C_ * T_ + 64];   // x norm, transposed [b][ch][t]
// Kernel slab in FINAL per-k layout: [k][s][8 x float4] = 128B per (k,s) entry:
//   float2 e=0..7 : broadcast pairs (-kn,-kn) for c=0..7
//   float2 e=8    : (q2/2, q2/2)
//   e=9..15       : padding (never read)
__device__ float4 g_slab[KSZ_ * S_ * 8];

// ---- packed f32x2 helpers (sm_100a) ---------------------------------------
__device__ __forceinline__ unsigned long long pk2(float lo, float hi) {
    unsigned long long r;
    asm("mov.b64 %0, {%1, %2};" : "=l"(r) : "f"(lo), "f"(hi));
    return r;
}
__device__ __forceinline__ unsigned long long fma2(unsigned long long a,
                                                   unsigned long long b,
                                                   unsigned long long c) {
    unsigned long long d;
    asm("fma.rn.f32x2 %0, %1, %2, %3;" : "=l"(d) : "l"(a), "l"(b), "l"(c));
    return d;
}
__device__ __forceinline__ unsigned long long mul2(unsigned long long a,
                                                   unsigned long long b) {
    unsigned long long d;
    asm("mul.rn.f32x2 %0, %1, %2;" : "=l"(d) : "l"(a), "l"(b));
    return d;
}
__device__ __forceinline__ void unpk2(unsigned long long v, float& lo, float& hi) {
    asm("mov.b64 {%0, %1}, %2;" : "=f"(lo), "=f"(hi) : "l"(v));
}

// ---- warp reduction (sum) -------------------------------------------------
__device__ __forceinline__ float wred(float v) {
    v += __shfl_xor_sync(0xFFFFFFFF, v, 16);
    v += __shfl_xor_sync(0xFFFFFFFF, v, 8);
    v += __shfl_xor_sync(0xFFFFFFFF, v, 4);
    v += __shfl_xor_sync(0xFFFFFFFF, v, 2);
    v += __shfl_xor_sync(0xFFFFFFFF, v, 1);
    return v;
}

// ---------------------------------------------------------------------------
// Prep: blocks [0,128) normalize x per (b,ch) over T and transpose;
//       blocks [128,192) normalize kernel per s, writing the padded slab
//       layout (negated broadcast pairs + hq2). Shuffle-based reductions.
// ---------------------------------------------------------------------------
__global__ __launch_bounds__(256) void lsd_prep(const float* __restrict__ x,
                                                const float* __restrict__ kern) {
    const int bid = blockIdx.x;
    const int tid = threadIdx.x;
    const int lid = tid & 31;
    const int wid = tid >> 5;
    __shared__ float pr0[8];
    __shared__ float pr1[8];
    __shared__ float stats[2];          // mean, inv
    __shared__ float kns[256];

    if (bid < B_ * C_) {
        const int b = bid >> 3, ch = bid & 7;
        const float v0 = x[(b * T_ + tid) * C_ + ch];
        const float v1 = x[(b * T_ + tid + 256) * C_ + ch];
        const float s0 = wred(v0 + v1);
        const float s1 = wred(v0 * v0 + v1 * v1);
        if (lid == 0) { pr0[wid] = s0; pr1[wid] = s1; }
        __syncthreads();
        if (wid == 0) {
            float a0 = (lid < 8) ? pr0[lid] : 0.0f;
            float a1 = (lid < 8) ? pr1[lid] : 0.0f;
            a0 = wred(a0); a1 = wred(a1);
            if (lid == 0) {
                const float mean = a0 * (1.0f / T_);
                const float var  = a1 * (1.0f / T_) - mean * mean;
                stats[0] = mean;
                stats[1] = 1.0f / (sqrtf(fmaxf(var, 0.0f)) + EPSF);
            }
        }
        __syncthreads();
        const float mean = stats[0], inv = stats[1];
        float* xr = &g_xt[(b * C_ + ch) * T_];
        xr[tid]       = (v0 - mean) * inv;
        xr[tid + 256] = (v1 - mean) * inv;
    } else {
        const int s = bid - B_ * C_;
        const float v = kern[s * 256 + tid];
        const float s0 = wred(v);
        const float s1 = wred(v * v);
        if (lid == 0) { pr0[wid] = s0; pr1[wid] = s1; }
        __syncthreads();
        if (wid == 0) {
            float a0 = (lid < 8) ? pr0[lid] : 0.0f;
            float a1 = (lid < 8) ? pr1[lid] : 0.0f;
            a0 = wred(a0); a1 = wred(a1);
            if (lid == 0) {
                const float mean = a0 * (1.0f / 256.0f);
                const float var  = a1 * (1.0f / 256.0f) - mean * mean;
                stats[0] = mean;
                stats[1] = 1.0f / (sqrtf(fmaxf(var, 0.0f)) + EPSF);
            }
        }
        __syncthreads();
        const float kn = (v - stats[0]) * stats[1];
        kns[tid] = kn;
        // slab entry [k][s], float2 element c: (-kn, -kn)
        const int k = tid >> 3, c = tid & 7;
        ((float2*)g_slab)[(k * S_ + s) * 16 + c] = make_float2(-kn, -kn);
        __syncthreads();
        if (tid < KSZ_) {
            float q2 = 0.0f;
            #pragma unroll
            for (int c2 = 0; c2 < 8; c2++) {
                const float t = kns[tid * 8 + c2];
                q2 = fmaf(t, t, q2);
            }
            const float h = 0.5f * q2;
            ((float2*)g_slab)[(tid * S_ + s) * 16 + 8] = make_float2(h, h);
        }
    }
}

// ---------------------------------------------------------------------------
// Main, j=8 + SOFTWARE-PIPELINED q loads: each thread computes 8 consecutive
// t for one k over 16 s. s+1's five broadcast LDS are issued before s's FMA
// chain consumes the current q registers, hiding the 29-cyc LDS latency.
// __launch_bounds__(256,3): 84-reg budget for the double-buffered q set
// (grid 512 = 3.46 blocks/SM is the occupancy cap anyway, not registers).
//   grid = (32, 16):  blockIdx.y = b, blockIdx.x = tb*16 + kpair (tb in 0..1)
//   block = 256 thr = 8 warps: warp w -> kk = w>>2 (k = kpair*2+kk), sg = w&3
//   lane l handles t = tb*256 + l*8 + j, j in [0,8), over s-quarter sg (16 s).
// acc = hq2 + sum_c a[j+c]*(-q_c) pair;  out = p2 + 2*min.
// ---------------------------------------------------------------------------
__global__ __launch_bounds__(256, 3) void lsd_main(float* __restrict__ out) {
    const int tid = threadIdx.x;
    const int l   = tid & 31;
    const int w   = tid >> 5;
    const int kk  = w >> 2;                   // 0..1 (warp-uniform)
    const int sg  = w & 3;                    // 0..3 (warp-uniform)
    const int b   = blockIdx.y;
    const int tb  = blockIdx.x >> 4;          // 0..1
    const int kp  = blockIdx.x & 15;          // 0..15
    const int k   = kp * 2 + kk;              // warp-uniform
    const int ch  = k >> 2;
    const int m   = k & 3;

    __shared__ float4 smq4[2 * 64 * 8];       // 16KB: [kk][s][8 float4]
    __shared__ float s_mn[3 * 512];           // 6KB: [sg-1][kk*256 + l*8 + j]

    // ---- slab copy: 1024 float4, pure shift/mask indexing ----
    {
        const float4* __restrict__ gsl = g_slab;
        #pragma unroll
        for (int it = 0; it < 4; it++) {
            const int idx = tid + it * 256;
            const int kkf = idx >> 9;         // 0..1
            const int rest = idx & 511;
            smq4[idx] = gsl[(kp * 2 + kkf) * 512 + rest];
        }
    }

    // ---- window loads: 16 floats via 4 aligned float4 LDGs (15 used) ----
    const int t0     = tb * 256 + l * 8;
    const int wstart = t0 + 8 * m;            // multiple of 8 -> 16B aligned
    const float4* __restrict__ xv =
        (const float4*)(g_xt + (b * C_ + ch) * T_ + wstart);
    const float4 A = xv[0], Bv = xv[1], Cv = xv[2], Dv = xv[3];
    float wv[15];
    wv[0]  = A.x;  wv[1]  = A.y;  wv[2]  = A.z;  wv[3]  = A.w;
    wv[4]  = Bv.x; wv[5]  = Bv.y; wv[6]  = Bv.z; wv[7]  = Bv.w;
    wv[8]  = Cv.x; wv[9]  = Cv.y; wv[10] = Cv.z; wv[11] = Cv.w;
    wv[12] = Dv.x; wv[13] = Dv.y; wv[14] = Dv.z;

    unsigned long long a[14];
    #pragma unroll
    for (int i = 0; i < 14; i++) a[i] = pk2(wv[i], wv[i + 1]);

    __syncthreads();

    // warp-uniform smem base for this warp's S-quarter (16B units)
    const ulonglong2* __restrict__ qv =
        (const ulonglong2*)smq4 + (kk * 64 + sg * 16) * 8;

    float mn[8];
    #pragma unroll
    for (int j = 0; j < 8; j++) mn[j] = 3.4e38f;

    // ---- software-pipelined s-loop: prefetch s+1 before consuming s ----
    ulonglong2 u0 = qv[0], u1 = qv[1], u2 = qv[2], u3 = qv[3];
    unsigned long long hq2 = *(const unsigned long long*)(qv + 4);

    #pragma unroll
    for (int s = 0; s < 16; s++) {
        // issue next iteration's loads first (latency overlaps FMA chain)
        ulonglong2 n0, n1, n2, n3;
        unsigned long long nh;
        if (s < 15) {
            n0 = qv[(s + 1) * 8 + 0];
            n1 = qv[(s + 1) * 8 + 1];
            n2 = qv[(s + 1) * 8 + 2];
            n3 = qv[(s + 1) * 8 + 3];
            nh = *(const unsigned long long*)(qv + (s + 1) * 8 + 4);
        }

        // 4 packed accumulators for j-pairs (0,1),(2,3),(4,5),(6,7)
        unsigned long long accA = fma2(a[0], u0.x, hq2);
        unsigned long long accB = fma2(a[2], u0.x, hq2);
        unsigned long long accC = fma2(a[4], u0.x, hq2);
        unsigned long long accD = fma2(a[6], u0.x, hq2);
        accA = fma2(a[1], u0.y, accA);
        accB = fma2(a[3], u0.y, accB);
        accC = fma2(a[5], u0.y, accC);
        accD = fma2(a[7], u0.y, accD);
        accA = fma2(a[2], u1.x, accA);
        accB = fma2(a[4], u1.x, accB);
        accC = fma2(a[6], u1.x, accC);
        accD = fma2(a[8], u1.x, accD);
        accA = fma2(a[3], u1.y, accA);
        accB = fma2(a[5], u1.y, accB);
        accC = fma2(a[7], u1.y, accC);
        accD = fma2(a[9], u1.y, accD);
        accA = fma2(a[4], u2.x, accA);
        accB = fma2(a[6], u2.x, accB);
        accC = fma2(a[8], u2.x, accC);
        accD = fma2(a[10], u2.x, accD);
        accA = fma2(a[5], u2.y, accA);
        accB = fma2(a[7], u2.y, accB);
        accC = fma2(a[9], u2.y, accC);
        accD = fma2(a[11], u2.y, accD);
        accA = fma2(a[6], u3.x, accA);
        accB = fma2(a[8], u3.x, accB);
        accC = fma2(a[10], u3.x, accC);
        accD = fma2(a[12], u3.x, accD);
        accA = fma2(a[7], u3.y, accA);
        accB = fma2(a[9], u3.y, accB);
        accC = fma2(a[11], u3.y, accC);
        accD = fma2(a[13], u3.y, accD);

        float d0, d1;
        unpk2(accA, d0, d1);
        mn[0] = fminf(mn[0], d0);
        mn[1] = fminf(mn[1], d1);
        unpk2(accB, d0, d1);
        mn[2] = fminf(mn[2], d0);
        mn[3] = fminf(mn[3], d1);
        unpk2(accC, d0, d1);
        mn[4] = fminf(mn[4], d0);
        mn[5] = fminf(mn[5], d1);
        unpk2(accD, d0, d1);
        mn[6] = fminf(mn[6], d0);
        mn[7] = fminf(mn[7], d1);

        if (s < 15) { u0 = n0; u1 = n1; u2 = n2; u3 = n3; hq2 = nh; }
    }

    // merge the four S-quarters (index within block: kk*256 + l*8 + j)
    if (sg >= 1) {
        #pragma unroll
        for (int j = 0; j < 8; j++)
            s_mn[(sg - 1) * 512 + kk * 256 + l * 8 + j] = mn[j];
    }
    __syncthreads();
    if (sg == 0) {
        // packed p2 for j-pairs: pX from a[jb..jb+7]
        float p2j[8];
        #pragma unroll
        for (int jb = 0; jb < 8; jb += 2) {
            unsigned long long p = mul2(a[jb], a[jb]);
            #pragma unroll
            for (int c = 1; c < 8; c++) p = fma2(a[jb + c], a[jb + c], p);
            unpk2(p, p2j[jb], p2j[jb + 1]);
        }

        #pragma unroll
        for (int j = 0; j < 8; j++) {
            const int t = t0 + j;
            if (t < TOUT) {
                const int base = kk * 256 + l * 8 + j;
                float v = mn[j];
                v = fminf(v, s_mn[0 * 512 + base]);
                v = fminf(v, s_mn[1 * 512 + base]);
                v = fminf(v, s_mn[2 * 512 + base]);
                out[(b * TOUT + t) * KSZ_ + k] = fmaf(2.0f, v, p2j[j]);
            }
        }
    }
}

extern "C" void kernel_launch(void* const* d_in, const int* in_sizes, int n_in,
                              void* d_out, int out_size) {
    const float* x    = (const float*)d_in[0];   // (16, 512, 8) f32
    const float* kern = (const float*)d_in[1];   // (64, 32, 8) f32
    float* out = (float*)d_out;                  // (16, 481, 32) f32

    lsd_prep<<<B_ * C_ + S_, 256>>>(x, kern);
    dim3 grid(32, B_);                           // (tb, kpair) x b
    lsd_main<<<grid, 256>>>(out);
}

// round 13
// speedup vs baseline: 1.1374x; 1.1374x over previous
#include <cuda_runtime.h>

#define B_   16
#define T_   512
#define C_   8
#define S_   64
#define KSZ_ 32
#define TOUT 481
#define EPSF 1e-8f

// Scratch (allocation-free rule: __device__ globals). g_xt padded +64 so the
// 4x float4 window loads at the t-edge stay in-bounds (values masked at store).
__device__ float g_xt[B_ * C_ * T_ + 64];   // x norm, transposed [b][ch][t]
// Kernel slab in FINAL per-k layout: [k][s][8 x float4] = 128B per (k,s) entry:
//   float2 e=0..7 : broadcast pairs (-kn,-kn) for c=0..7
//   float2 e=8    : (q2/2, q2/2)
//   e=9..15       : padding (never read)
__device__ float4 g_slab[KSZ_ * S_ * 8];

// ---- packed f32x2 helpers (sm_100a) ---------------------------------------
__device__ __forceinline__ unsigned long long pk2(float lo, float hi) {
    unsigned long long r;
    asm("mov.b64 %0, {%1, %2};" : "=l"(r) : "f"(lo), "f"(hi));
    return r;
}
__device__ __forceinline__ unsigned long long fma2(unsigned long long a,
                                                   unsigned long long b,
                                                   unsigned long long c) {
    unsigned long long d;
    asm("fma.rn.f32x2 %0, %1, %2, %3;" : "=l"(d) : "l"(a), "l"(b), "l"(c));
    return d;
}
__device__ __forceinline__ unsigned long long mul2(unsigned long long a,
                                                   unsigned long long b) {
    unsigned long long d;
    asm("mul.rn.f32x2 %0, %1, %2;" : "=l"(d) : "l"(a), "l"(b));
    return d;
}
__device__ __forceinline__ void unpk2(unsigned long long v, float& lo, float& hi) {
    asm("mov.b64 {%0, %1}, %2;" : "=f"(lo), "=f"(hi) : "l"(v));
}

// ---- warp reduction (sum) -------------------------------------------------
__device__ __forceinline__ float wred(float v) {
    v += __shfl_xor_sync(0xFFFFFFFF, v, 16);
    v += __shfl_xor_sync(0xFFFFFFFF, v, 8);
    v += __shfl_xor_sync(0xFFFFFFFF, v, 4);
    v += __shfl_xor_sync(0xFFFFFFFF, v, 2);
    v += __shfl_xor_sync(0xFFFFFFFF, v, 1);
    return v;
}

// ---------------------------------------------------------------------------
// Prep: blocks [0,128) normalize x per (b,ch) over T and transpose;
//       blocks [128,192) normalize kernel per s, writing the padded slab
//       layout (negated broadcast pairs + hq2). Shuffle-based reductions.
// ---------------------------------------------------------------------------
__global__ __launch_bounds__(256) void lsd_prep(const float* __restrict__ x,
                                                const float* __restrict__ kern) {
    const int bid = blockIdx.x;
    const int tid = threadIdx.x;
    const int lid = tid & 31;
    const int wid = tid >> 5;
    __shared__ float pr0[8];
    __shared__ float pr1[8];
    __shared__ float stats[2];          // mean, inv
    __shared__ float kns[256];

    if (bid < B_ * C_) {
        const int b = bid >> 3, ch = bid & 7;
        const float v0 = x[(b * T_ + tid) * C_ + ch];
        const float v1 = x[(b * T_ + tid + 256) * C_ + ch];
        const float s0 = wred(v0 + v1);
        const float s1 = wred(v0 * v0 + v1 * v1);
        if (lid == 0) { pr0[wid] = s0; pr1[wid] = s1; }
        __syncthreads();
        if (wid == 0) {
            float a0 = (lid < 8) ? pr0[lid] : 0.0f;
            float a1 = (lid < 8) ? pr1[lid] : 0.0f;
            a0 = wred(a0); a1 = wred(a1);
            if (lid == 0) {
                const float mean = a0 * (1.0f / T_);
                const float var  = a1 * (1.0f / T_) - mean * mean;
                stats[0] = mean;
                stats[1] = 1.0f / (sqrtf(fmaxf(var, 0.0f)) + EPSF);
            }
        }
        __syncthreads();
        const float mean = stats[0], inv = stats[1];
        float* xr = &g_xt[(b * C_ + ch) * T_];
        xr[tid]       = (v0 - mean) * inv;
        xr[tid + 256] = (v1 - mean) * inv;
    } else {
        const int s = bid - B_ * C_;
        const float v = kern[s * 256 + tid];
        const float s0 = wred(v);
        const float s1 = wred(v * v);
        if (lid == 0) { pr0[wid] = s0; pr1[wid] = s1; }
        __syncthreads();
        if (wid == 0) {
            float a0 = (lid < 8) ? pr0[lid] : 0.0f;
            float a1 = (lid < 8) ? pr1[lid] : 0.0f;
            a0 = wred(a0); a1 = wred(a1);
            if (lid == 0) {
                const float mean = a0 * (1.0f / 256.0f);
                const float var  = a1 * (1.0f / 256.0f) - mean * mean;
                stats[0] = mean;
                stats[1] = 1.0f / (sqrtf(fmaxf(var, 0.0f)) + EPSF);
            }
        }
        __syncthreads();
        const float kn = (v - stats[0]) * stats[1];
        kns[tid] = kn;
        // slab entry [k][s], float2 element c: (-kn, -kn)
        const int k = tid >> 3, c = tid & 7;
        ((float2*)g_slab)[(k * S_ + s) * 16 + c] = make_float2(-kn, -kn);
        __syncthreads();
        if (tid < KSZ_) {
            float q2 = 0.0f;
            #pragma unroll
            for (int c2 = 0; c2 < 8; c2++) {
                const float t = kns[tid * 8 + c2];
                q2 = fmaf(t, t, q2);
            }
            const float h = 0.5f * q2;
            ((float2*)g_slab)[(tid * S_ + s) * 16 + 8] = make_float2(h, h);
        }
    }
}

// ---------------------------------------------------------------------------
// Main, j=8, 128-THREAD BLOCKS (one k per block, k/ch/m block-uniform):
//   grid = (64, 16):  blockIdx.y = b, blockIdx.x = tb*32 + k (tb in 0..1)
//   block = 128 thr = 4 warps: warp w = sg (S-quarter, 16 s each)
//   lane l handles t = tb*256 + l*8 + j, j in [0,8).
// 8 blocks/SM at 64 regs (RF-exact) -> up to 32 warps/SM, 0.86 waves.
// Slab (1 k x 64 s x 128B = 8KB) staged in smem; broadcast LDS in hot loop.
// acc = hq2 + sum_c a[j+c]*(-q_c) pair;  out = p2 + 2*min.
// ---------------------------------------------------------------------------
__global__ __launch_bounds__(128, 8) void lsd_main(float* __restrict__ out) {
    const int tid = threadIdx.x;
    const int l   = tid & 31;
    const int sg  = tid >> 5;                 // 0..3 (warp-uniform)
    const int b   = blockIdx.y;
    const int tb  = blockIdx.x >> 5;          // 0..1
    const int k   = blockIdx.x & 31;          // BLOCK-uniform
    const int ch  = k >> 2;
    const int m   = k & 3;

    __shared__ float4 smq4[64 * 8];           // 8KB: [s][8 float4]
    __shared__ float s_mn[3 * 256];           // 3KB: [sg-1][l*8 + j]

    // ---- slab copy: 512 float4 over 128 threads ----
    {
        const float4* __restrict__ gsl = g_slab + k * 512;
        #pragma unroll
        for (int it = 0; it < 4; it++) {
            const int idx = tid + it * 128;
            smq4[idx] = gsl[idx];
        }
    }

    // ---- window loads: 16 floats via 4 aligned float4 LDGs (15 used) ----
    const int t0     = tb * 256 + l * 8;
    const int wstart = t0 + 8 * m;            // multiple of 8 -> 16B aligned
    const float4* __restrict__ xv =
        (const float4*)(g_xt + (b * C_ + ch) * T_ + wstart);
    const float4 A = xv[0], Bv = xv[1], Cv = xv[2], Dv = xv[3];
    float wv[15];
    wv[0]  = A.x;  wv[1]  = A.y;  wv[2]  = A.z;  wv[3]  = A.w;
    wv[4]  = Bv.x; wv[5]  = Bv.y; wv[6]  = Bv.z; wv[7]  = Bv.w;
    wv[8]  = Cv.x; wv[9]  = Cv.y; wv[10] = Cv.z; wv[11] = Cv.w;
    wv[12] = Dv.x; wv[13] = Dv.y; wv[14] = Dv.z;

    unsigned long long a[14];
    #pragma unroll
    for (int i = 0; i < 14; i++) a[i] = pk2(wv[i], wv[i + 1]);

    __syncthreads();

    // warp-uniform smem base for this warp's S-quarter (16B units)
    const ulonglong2* __restrict__ qv =
        (const ulonglong2*)smq4 + sg * 16 * 8;

    float mn[8];
    #pragma unroll
    for (int j = 0; j < 8; j++) mn[j] = 3.4e38f;

    #pragma unroll
    for (int s = 0; s < 16; s++) {
        const ulonglong2 u0 = qv[s * 8 + 0];      // qq0, qq1 (negated)
        const ulonglong2 u1 = qv[s * 8 + 1];      // qq2, qq3
        const ulonglong2 u2 = qv[s * 8 + 2];      // qq4, qq5
        const ulonglong2 u3 = qv[s * 8 + 3];      // qq6, qq7
        const unsigned long long hq2 =
            *(const unsigned long long*)(qv + s * 8 + 4);

        // 4 packed accumulators for j-pairs (0,1),(2,3),(4,5),(6,7)
        unsigned long long accA = fma2(a[0], u0.x, hq2);
        unsigned long long accB = fma2(a[2], u0.x, hq2);
        unsigned long long accC = fma2(a[4], u0.x, hq2);
        unsigned long long accD = fma2(a[6], u0.x, hq2);
        accA = fma2(a[1], u0.y, accA);
        accB = fma2(a[3], u0.y, accB);
        accC = fma2(a[5], u0.y, accC);
        accD = fma2(a[7], u0.y, accD);
        accA = fma2(a[2], u1.x, accA);
        accB = fma2(a[4], u1.x, accB);
        accC = fma2(a[6], u1.x, accC);
        accD = fma2(a[8], u1.x, accD);
        accA = fma2(a[3], u1.y, accA);
        accB = fma2(a[5], u1.y, accB);
        accC = fma2(a[7], u1.y, accC);
        accD = fma2(a[9], u1.y, accD);
        accA = fma2(a[4], u2.x, accA);
        accB = fma2(a[6], u2.x, accB);
        accC = fma2(a[8], u2.x, accC);
        accD = fma2(a[10], u2.x, accD);
        accA = fma2(a[5], u2.y, accA);
        accB = fma2(a[7], u2.y, accB);
        accC = fma2(a[9], u2.y, accC);
        accD = fma2(a[11], u2.y, accD);
        accA = fma2(a[6], u3.x, accA);
        accB = fma2(a[8], u3.x, accB);
        accC = fma2(a[10], u3.x, accC);
        accD = fma2(a[12], u3.x, accD);
        accA = fma2(a[7], u3.y, accA);
        accB = fma2(a[9], u3.y, accB);
        accC = fma2(a[11], u3.y, accC);
        accD = fma2(a[13], u3.y, accD);

        float d0, d1;
        unpk2(accA, d0, d1);
        mn[0] = fminf(mn[0], d0);
        mn[1] = fminf(mn[1], d1);
        unpk2(accB, d0, d1);
        mn[2] = fminf(mn[2], d0);
        mn[3] = fminf(mn[3], d1);
        unpk2(accC, d0, d1);
        mn[4] = fminf(mn[4], d0);
        mn[5] = fminf(mn[5], d1);
        unpk2(accD, d0, d1);
        mn[6] = fminf(mn[6], d0);
        mn[7] = fminf(mn[7], d1);
    }

    // merge the four S-quarters (index within block: l*8 + j)
    if (sg >= 1) {
        #pragma unroll
        for (int j = 0; j < 8; j++)
            s_mn[(sg - 1) * 256 + l * 8 + j] = mn[j];
    }
    __syncthreads();
    if (sg == 0) {
        // packed p2 for j-pairs: pX from a[jb..jb+7]
        float p2j[8];
        #pragma unroll
        for (int jb = 0; jb < 8; jb += 2) {
            unsigned long long p = mul2(a[jb], a[jb]);
            #pragma unroll
            for (int c = 1; c < 8; c++) p = fma2(a[jb + c], a[jb + c], p);
            unpk2(p, p2j[jb], p2j[jb + 1]);
        }

        #pragma unroll
        for (int j = 0; j < 8; j++) {
            const int t = t0 + j;
            if (t < TOUT) {
                const int base = l * 8 + j;
                float v = mn[j];
                v = fminf(v, s_mn[0 * 256 + base]);
                v = fminf(v, s_mn[1 * 256 + base]);
                v = fminf(v, s_mn[2 * 256 + base]);
                out[(b * TOUT + t) * KSZ_ + k] = fmaf(2.0f, v, p2j[j]);
            }
        }
    }
}

extern "C" void kernel_launch(void* const* d_in, const int* in_sizes, int n_in,
                              void* d_out, int out_size) {
    const float* x    = (const float*)d_in[0];   // (16, 512, 8) f32
    const float* kern = (const float*)d_in[1];   // (64, 32, 8) f32
    float* out = (float*)d_out;                  // (16, 481, 32) f32

    lsd_prep<<<B_ * C_ + S_, 256>>>(x, kern);
    dim3 grid(64, B_);                           // (tb*32 + k) x b
    lsd_main<<<grid, 128>>>(out);
}